// round 15
// baseline (speedup 1.0000x reference)
#include <cuda_runtime.h>

#define PP 32768
#define LL 16
#define KK 8
#define HH 128
#define YW 64           // width of pre-projected gather payload y = h @ ne_w1
#define NB (PP / 32)    // 1024 blocks in the layer grid

// h only needed for layer 15 (final head); y carries layers 0..14.
__device__ float g_h[(long long)LL * PP * HH];   // 256 MiB
__device__ float g_y[(long long)LL * PP * YW];   // 128 MiB
__device__ unsigned g_ctr;                        // grid-barrier counter

__device__ __forceinline__ float lrelu(float x) { return x > 0.0f ? x : 0.1f * x; }
__device__ __forceinline__ float relu_(float x) { return x > 0.0f ? x : 0.0f; }

// Software grid barrier: barrier #b (1-based) completes when g_ctr >= b*NB.
// Monotonic within a launch (no reset races); g_ctr zeroed by k_reset per launch.
__device__ __forceinline__ void gbar(unsigned b) {
    __threadfence();              // make this thread's g_y writes visible
    __syncthreads();
    if (threadIdx.x == 0) {
        atomicAdd(&g_ctr, 1u);
        volatile unsigned* p = &g_ctr;
        while (*p < b * (unsigned)NB) __nanosleep(64);
    }
    __syncthreads();
}

__global__ void k_reset() { g_ctr = 0u; }

// ---------------------------------------------------------------------------
// k_init: h0 = mlp2(delay, pi) (in smem), then y0 = h0 @ ne_w1 -> g_y.
// ---------------------------------------------------------------------------
__global__ void __launch_bounds__(256, 1)
k_init(const float* __restrict__ delay,
       const float* __restrict__ w1, const float* __restrict__ b1,
       const float* __restrict__ w2, const float* __restrict__ b2,
       const float* __restrict__ ne_w1)
{
    extern __shared__ float smem[];
    float* s_t1 = smem;            // 64*64  = 4096
    float* s_w2 = smem + 4096;     // 64*128 = 8192
    float* s_b2 = smem + 12288;    // 128
    float* s_h  = smem + 12416;    // 64*128 = 8192

    const int tid  = threadIdx.x;
    const int row0 = blockIdx.x * 64;

    for (int i = tid; i < 2048; i += 256)
        ((float4*)s_w2)[i] = ((const float4*)w2)[i];
    for (int i = tid; i < 128; i += 256) s_b2[i] = b2[i];
    for (int i = tid; i < 64 * 64; i += 256) {
        int r = i >> 6, c = i & 63;
        s_t1[i] = lrelu(delay[row0 + r] * w1[c] + b1[c]);
    }
    __syncthreads();

    const int w = tid >> 5, l = tid & 31;
    const int r0 = w * 8, c0 = l * 4;
    float acc[8][4];
#pragma unroll
    for (int r = 0; r < 8; r++)
#pragma unroll
        for (int c = 0; c < 4; c++) acc[r][c] = 0.0f;

#pragma unroll 4
    for (int k = 0; k < 64; k += 2) {
        float4 w0  = *(const float4*)(s_w2 + k * 128 + c0);
        float4 w1v = *(const float4*)(s_w2 + (k + 1) * 128 + c0);
#pragma unroll
        for (int r = 0; r < 8; r++) {
            float2 a = *(const float2*)(s_t1 + (r0 + r) * 64 + k);
            acc[r][0] = fmaf(a.x, w0.x, acc[r][0]); acc[r][0] = fmaf(a.y, w1v.x, acc[r][0]);
            acc[r][1] = fmaf(a.x, w0.y, acc[r][1]); acc[r][1] = fmaf(a.y, w1v.y, acc[r][1]);
            acc[r][2] = fmaf(a.x, w0.z, acc[r][2]); acc[r][2] = fmaf(a.y, w1v.z, acc[r][2]);
            acc[r][3] = fmaf(a.x, w0.w, acc[r][3]); acc[r][3] = fmaf(a.y, w1v.w, acc[r][3]);
        }
    }
#pragma unroll
    for (int r = 0; r < 8; r++) {
        float4 o;
        o.x = acc[r][0] + s_b2[c0 + 0];
        o.y = acc[r][1] + s_b2[c0 + 1];
        o.z = acc[r][2] + s_b2[c0 + 2];
        o.w = acc[r][3] + s_b2[c0 + 3];
        *(float4*)(s_h + (r0 + r) * 128 + c0) = o;
    }
    __syncthreads();

    const int r1 = r0 + (l >> 4) * 4;
    const int cg = (l & 15) * 4;
    float accY[4][4];
#pragma unroll
    for (int i = 0; i < 4; i++)
#pragma unroll
        for (int c = 0; c < 4; c++) accY[i][c] = 0.f;
#pragma unroll 2
    for (int k = 0; k < 128; k += 4) {
        float4 wv0 = *(const float4*)(ne_w1 + (k + 0) * 64 + cg);
        float4 wv1 = *(const float4*)(ne_w1 + (k + 1) * 64 + cg);
        float4 wv2 = *(const float4*)(ne_w1 + (k + 2) * 64 + cg);
        float4 wv3 = *(const float4*)(ne_w1 + (k + 3) * 64 + cg);
#pragma unroll
        for (int i = 0; i < 4; i++) {
            float4 a = *(const float4*)(s_h + (r1 + i) * 128 + k);
            accY[i][0] = fmaf(a.x, wv0.x, accY[i][0]); accY[i][0] = fmaf(a.y, wv1.x, accY[i][0]);
            accY[i][0] = fmaf(a.z, wv2.x, accY[i][0]); accY[i][0] = fmaf(a.w, wv3.x, accY[i][0]);
            accY[i][1] = fmaf(a.x, wv0.y, accY[i][1]); accY[i][1] = fmaf(a.y, wv1.y, accY[i][1]);
            accY[i][1] = fmaf(a.z, wv2.y, accY[i][1]); accY[i][1] = fmaf(a.w, wv3.y, accY[i][1]);
            accY[i][2] = fmaf(a.x, wv0.z, accY[i][2]); accY[i][2] = fmaf(a.y, wv1.z, accY[i][2]);
            accY[i][2] = fmaf(a.z, wv2.z, accY[i][2]); accY[i][2] = fmaf(a.w, wv3.z, accY[i][2]);
            accY[i][3] = fmaf(a.x, wv0.w, accY[i][3]); accY[i][3] = fmaf(a.y, wv1.w, accY[i][3]);
            accY[i][3] = fmaf(a.z, wv2.w, accY[i][3]); accY[i][3] = fmaf(a.w, wv3.w, accY[i][3]);
        }
    }
#pragma unroll
    for (int i = 0; i < 4; i++)
        *(float4*)(g_y + (long long)(row0 + r1 + i) * YW + cg) =
            make_float4(accY[i][0], accY[i][1], accY[i][2], accY[i][3]);
}

// ---------------------------------------------------------------------------
// Shared layer building blocks (R14-proven). smem layout:
//   s_t 4096 | s_ft 1024 | s_b1 128 | s_b2 128 | s_pred 256 = 5632 floats
// ---------------------------------------------------------------------------
__device__ __forceinline__ void preload_layer(float* smem, int tid, int lo, int row0,
                                              const int* __restrict__ pred,
                                              const float* __restrict__ feat)
{
    float* s_ft  = smem + 4096;
    int*   s_pred = (int*)(smem + 5376);
    for (int i = tid; i < 256; i += 128) {
        int r = i >> 3, c4 = i & 7;
        ((float4*)(s_ft + r * 32))[c4] =
            *((const float4*)(feat + (long long)(lo + row0 + r) * 32) + c4);
    }
    for (int i = tid; i < 256; i += 128)
        s_pred[i] = pred[(long long)row0 * KK + i];
}

template <bool LAST>
__device__ __forceinline__ void compute_layer(float* smem, int tid, int lo, int row0,
        const float* __restrict__ ne_w1, const float* __restrict__ ne_w2,
        const float* __restrict__ sf_w1, const float* __restrict__ sf_w2)
{
    float* s_t   = smem;
    float* s_ft  = smem + 4096;
    float* s_b1  = smem + 5120;
    float* s_b2  = smem + 5248;
    int*   s_pred = (int*)(smem + 5376);

    // ---- gather-mean of y (64-wide) + fused bias + lrelu -> t_ne ----
    float4* t4 = (float4*)s_t;
#pragma unroll
    for (int j = 0; j < 4; j++) {
        int task = tid + j * 128;
        int r = task >> 4, c4 = task & 15;
        const int* pr = s_pred + r * 8;
        float x = 0.f, y = 0.f, z = 0.f, s = 0.f;
#pragma unroll
        for (int k = 0; k < 8; k++) {
            const float4 v = *((const float4*)(g_y + (long long)pr[k] * YW) + c4);
            x += v.x; y += v.y; z += v.z; s += v.w;
        }
        const int c = c4 * 4;
        float4 o;
        o.x = lrelu(x * 0.125f + s_b1[c + 0]);
        o.y = lrelu(y * 0.125f + s_b1[c + 1]);
        o.z = lrelu(z * 0.125f + s_b1[c + 2]);
        o.w = lrelu(s * 0.125f + s_b1[c + 3]);
        t4[r * 32 + c4] = o;
    }

    const int w = tid >> 5, l = tid & 31;
    const int r0 = w * 8;
    const int r1 = r0 + (l >> 4) * 4;
    const int cg = (l & 15) * 4;

    // ---- t_sf = lrelu(feat @ sf_w1 + b) ----
    {
        float accB[4][4];
#pragma unroll
        for (int i = 0; i < 4; i++)
#pragma unroll
            for (int c = 0; c < 4; c++) accB[i][c] = 0.f;
#pragma unroll 2
        for (int k = 0; k < 32; k += 4) {
            float4 wv0 = *(const float4*)(sf_w1 + (k + 0) * 64 + cg);
            float4 wv1 = *(const float4*)(sf_w1 + (k + 1) * 64 + cg);
            float4 wv2 = *(const float4*)(sf_w1 + (k + 2) * 64 + cg);
            float4 wv3 = *(const float4*)(sf_w1 + (k + 3) * 64 + cg);
#pragma unroll
            for (int i = 0; i < 4; i++) {
                float4 a = *(const float4*)(s_ft + (r1 + i) * 32 + k);
                accB[i][0] = fmaf(a.x, wv0.x, accB[i][0]); accB[i][0] = fmaf(a.y, wv1.x, accB[i][0]);
                accB[i][0] = fmaf(a.z, wv2.x, accB[i][0]); accB[i][0] = fmaf(a.w, wv3.x, accB[i][0]);
                accB[i][1] = fmaf(a.x, wv0.y, accB[i][1]); accB[i][1] = fmaf(a.y, wv1.y, accB[i][1]);
                accB[i][1] = fmaf(a.z, wv2.y, accB[i][1]); accB[i][1] = fmaf(a.w, wv3.y, accB[i][1]);
                accB[i][2] = fmaf(a.x, wv0.z, accB[i][2]); accB[i][2] = fmaf(a.y, wv1.z, accB[i][2]);
                accB[i][2] = fmaf(a.z, wv2.z, accB[i][2]); accB[i][2] = fmaf(a.w, wv3.z, accB[i][2]);
                accB[i][3] = fmaf(a.x, wv0.w, accB[i][3]); accB[i][3] = fmaf(a.y, wv1.w, accB[i][3]);
                accB[i][3] = fmaf(a.z, wv2.w, accB[i][3]); accB[i][3] = fmaf(a.w, wv3.w, accB[i][3]);
            }
        }
#pragma unroll
        for (int i = 0; i < 4; i++) {
            float4 o;
            o.x = lrelu(accB[i][0] + s_b1[64 + cg + 0]);
            o.y = lrelu(accB[i][1] + s_b1[64 + cg + 1]);
            o.z = lrelu(accB[i][2] + s_b1[64 + cg + 2]);
            o.w = lrelu(accB[i][3] + s_b1[64 + cg + 3]);
            *(float4*)(s_t + (r1 + i) * 128 + 64 + cg) = o;
        }
    }
    __syncthreads();   // t complete block-wide

    // ---- stage 2: hn = t @ [ne_w2; sf_w2] ----
    const int c0 = l * 4;
    float acc[8][4];
#pragma unroll
    for (int r = 0; r < 8; r++) { acc[r][0] = acc[r][1] = acc[r][2] = acc[r][3] = 0.f; }

#pragma unroll 2
    for (int k = 0; k < 64; k += 4) {
        float4 wv0 = *(const float4*)(ne_w2 + (k + 0) * 128 + c0);
        float4 wv1 = *(const float4*)(ne_w2 + (k + 1) * 128 + c0);
        float4 wv2 = *(const float4*)(ne_w2 + (k + 2) * 128 + c0);
        float4 wv3 = *(const float4*)(ne_w2 + (k + 3) * 128 + c0);
#pragma unroll
        for (int r = 0; r < 8; r++) {
            float4 a = *(const float4*)(s_t + (r0 + r) * 128 + k);
            acc[r][0] = fmaf(a.x, wv0.x, acc[r][0]); acc[r][0] = fmaf(a.y, wv1.x, acc[r][0]);
            acc[r][0] = fmaf(a.z, wv2.x, acc[r][0]); acc[r][0] = fmaf(a.w, wv3.x, acc[r][0]);
            acc[r][1] = fmaf(a.x, wv0.y, acc[r][1]); acc[r][1] = fmaf(a.y, wv1.y, acc[r][1]);
            acc[r][1] = fmaf(a.z, wv2.y, acc[r][1]); acc[r][1] = fmaf(a.w, wv3.y, acc[r][1]);
            acc[r][2] = fmaf(a.x, wv0.z, acc[r][2]); acc[r][2] = fmaf(a.y, wv1.z, acc[r][2]);
            acc[r][2] = fmaf(a.z, wv2.z, acc[r][2]); acc[r][2] = fmaf(a.w, wv3.z, acc[r][2]);
            acc[r][3] = fmaf(a.x, wv0.w, acc[r][3]); acc[r][3] = fmaf(a.y, wv1.w, acc[r][3]);
            acc[r][3] = fmaf(a.z, wv2.w, acc[r][3]); acc[r][3] = fmaf(a.w, wv3.w, acc[r][3]);
        }
    }
#pragma unroll 2
    for (int k = 0; k < 64; k += 4) {
        float4 wv0 = *(const float4*)(sf_w2 + (k + 0) * 128 + c0);
        float4 wv1 = *(const float4*)(sf_w2 + (k + 1) * 128 + c0);
        float4 wv2 = *(const float4*)(sf_w2 + (k + 2) * 128 + c0);
        float4 wv3 = *(const float4*)(sf_w2 + (k + 3) * 128 + c0);
#pragma unroll
        for (int r = 0; r < 8; r++) {
            float4 a = *(const float4*)(s_t + (r0 + r) * 128 + 64 + k);
            acc[r][0] = fmaf(a.x, wv0.x, acc[r][0]); acc[r][0] = fmaf(a.y, wv1.x, acc[r][0]);
            acc[r][0] = fmaf(a.z, wv2.x, acc[r][0]); acc[r][0] = fmaf(a.w, wv3.x, acc[r][0]);
            acc[r][1] = fmaf(a.x, wv0.y, acc[r][1]); acc[r][1] = fmaf(a.y, wv1.y, acc[r][1]);
            acc[r][1] = fmaf(a.z, wv2.y, acc[r][1]); acc[r][1] = fmaf(a.w, wv3.y, acc[r][1]);
            acc[r][2] = fmaf(a.x, wv0.z, acc[r][2]); acc[r][2] = fmaf(a.y, wv1.z, acc[r][2]);
            acc[r][2] = fmaf(a.z, wv2.z, acc[r][2]); acc[r][2] = fmaf(a.w, wv3.z, acc[r][2]);
            acc[r][3] = fmaf(a.x, wv0.w, acc[r][3]); acc[r][3] = fmaf(a.y, wv1.w, acc[r][3]);
            acc[r][3] = fmaf(a.z, wv2.w, acc[r][3]); acc[r][3] = fmaf(a.w, wv3.w, acc[r][3]);
        }
    }

    if (LAST) {
#pragma unroll
        for (int r = 0; r < 8; r++) {
            float4 o;
            o.x = acc[r][0] + s_b2[c0 + 0];
            o.y = acc[r][1] + s_b2[c0 + 1];
            o.z = acc[r][2] + s_b2[c0 + 2];
            o.w = acc[r][3] + s_b2[c0 + 3];
            *(float4*)(g_h + (long long)(lo + row0 + r0 + r) * HH + c0) = o;
        }
    } else {
#pragma unroll
        for (int r = 0; r < 8; r++) {
            float4 o;
            o.x = relu_(acc[r][0] + s_b2[c0 + 0]);
            o.y = relu_(acc[r][1] + s_b2[c0 + 1]);
            o.z = relu_(acc[r][2] + s_b2[c0 + 2]);
            o.w = relu_(acc[r][3] + s_b2[c0 + 3]);
            *(float4*)(s_t + (r0 + r) * 128 + c0) = o;
        }
        __syncwarp();

        float accY[4][4];
#pragma unroll
        for (int i = 0; i < 4; i++)
#pragma unroll
            for (int c = 0; c < 4; c++) accY[i][c] = 0.f;
#pragma unroll 2
        for (int k = 0; k < 128; k += 4) {
            float4 wv0 = *(const float4*)(ne_w1 + (k + 0) * 64 + cg);
            float4 wv1 = *(const float4*)(ne_w1 + (k + 1) * 64 + cg);
            float4 wv2 = *(const float4*)(ne_w1 + (k + 2) * 64 + cg);
            float4 wv3 = *(const float4*)(ne_w1 + (k + 3) * 64 + cg);
#pragma unroll
            for (int i = 0; i < 4; i++) {
                float4 a = *(const float4*)(s_t + (r1 + i) * 128 + k);
                accY[i][0] = fmaf(a.x, wv0.x, accY[i][0]); accY[i][0] = fmaf(a.y, wv1.x, accY[i][0]);
                accY[i][0] = fmaf(a.z, wv2.x, accY[i][0]); accY[i][0] = fmaf(a.w, wv3.x, accY[i][0]);
                accY[i][1] = fmaf(a.x, wv0.y, accY[i][1]); accY[i][1] = fmaf(a.y, wv1.y, accY[i][1]);
                accY[i][1] = fmaf(a.z, wv2.y, accY[i][1]); accY[i][1] = fmaf(a.w, wv3.y, accY[i][1]);
                accY[i][2] = fmaf(a.x, wv0.z, accY[i][2]); accY[i][2] = fmaf(a.y, wv1.z, accY[i][2]);
                accY[i][2] = fmaf(a.z, wv2.z, accY[i][2]); accY[i][2] = fmaf(a.w, wv3.z, accY[i][2]);
                accY[i][3] = fmaf(a.x, wv0.w, accY[i][3]); accY[i][3] = fmaf(a.y, wv1.w, accY[i][3]);
                accY[i][3] = fmaf(a.z, wv2.w, accY[i][3]); accY[i][3] = fmaf(a.w, wv3.w, accY[i][3]);
            }
        }
#pragma unroll
        for (int i = 0; i < 4; i++)
            *(float4*)(g_y + (long long)(lo + row0 + r1 + i) * YW + cg) =
                make_float4(accY[i][0], accY[i][1], accY[i][2], accY[i][3]);
    }
}

// ---------------------------------------------------------------------------
// Fallback per-layer kernel (R14-proven path)
// ---------------------------------------------------------------------------
template <bool LAST>
__global__ void __launch_bounds__(128, 7)
k_layer(int lo,
        const int*   __restrict__ pred,
        const float* __restrict__ feat,
        const float* __restrict__ ne_w1, const float* __restrict__ ne_b1,
        const float* __restrict__ ne_w2, const float* __restrict__ ne_b2,
        const float* __restrict__ sf_w1, const float* __restrict__ sf_b1,
        const float* __restrict__ sf_w2, const float* __restrict__ sf_b2)
{
    extern __shared__ float smem[];
    const int tid  = threadIdx.x;
    const int row0 = blockIdx.x * 32;

    preload_layer(smem, tid, lo, row0, pred, feat);
    if (tid < 128) {
        smem[5120 + tid] = (tid < 64) ? ne_b1[tid] : sf_b1[tid - 64];
        smem[5248 + tid] = ne_b2[tid] + sf_b2[tid];
    }
    __syncthreads();
    compute_layer<LAST>(smem, tid, lo, row0, ne_w1, ne_w2, sf_w1, sf_w2);
}

// ---------------------------------------------------------------------------
// Persistent fused chain: layers 1..15 in one launch, software grid barrier.
// Requires all NB blocks co-resident (verified host-side before use).
// ---------------------------------------------------------------------------
__global__ void __launch_bounds__(128, 7)
k_all(const int*   __restrict__ pred_all,
      const float* __restrict__ feat,
      const float* __restrict__ ne_w1, const float* __restrict__ ne_b1,
      const float* __restrict__ ne_w2, const float* __restrict__ ne_b2,
      const float* __restrict__ sf_w1, const float* __restrict__ sf_b1,
      const float* __restrict__ sf_w2, const float* __restrict__ sf_b2)
{
    extern __shared__ float smem[];
    const int tid  = threadIdx.x;
    const int row0 = blockIdx.x * 32;

    if (tid < 128) {
        smem[5120 + tid] = (tid < 64) ? ne_b1[tid] : sf_b1[tid - 64];
        smem[5248 + tid] = ne_b2[tid] + sf_b2[tid];
    }
    // preload layer 1's ft/pred
    preload_layer(smem, tid, PP, row0, pred_all, feat);
    __syncthreads();

#pragma unroll 1
    for (int i = 1; i < LL - 1; i++) {
        compute_layer<false>(smem, tid, i * PP, row0,
                             ne_w1, ne_w2, sf_w1, sf_w2);
        // prefetch next layer's ft/pred BEFORE the barrier (barrier-independent)
        preload_layer(smem, tid, (i + 1) * PP, row0,
                      pred_all + (long long)i * PP * KK, feat);
        gbar((unsigned)i);   // release g_y writes; acquire for next gather
    }
    compute_layer<true>(smem, tid, (LL - 1) * PP, row0,
                        ne_w1, ne_w2, sf_w1, sf_w2);
}

// ---------------------------------------------------------------------------
// Final head (unchanged; reads g_h layer-15 rows)
// ---------------------------------------------------------------------------
__global__ void __launch_bounds__(256, 1)
k_final(const float* __restrict__ PO,
        const float* __restrict__ gl_w1, const float* __restrict__ gl_b1,
        const float* __restrict__ gl_w2, const float* __restrict__ gl_b2,
        const float* __restrict__ out_w1, const float* __restrict__ out_b1,
        const float* __restrict__ out_w2, const float* __restrict__ out_b2,
        float* __restrict__ out)
{
    extern __shared__ float smem[];
    float* s_x   = smem;             // 64*256
    float* s_w   = s_x + 16384;      // 64*128
    float* s_t   = s_w + 8192;       // 64*132
    float* s_g1  = s_t + 8448;       // 64*64
    float* s_gb2 = s_g1 + 4096;      // 128
    float* s_ob1 = s_gb2 + 128;      // 128
    float* s_ow2 = s_ob1 + 128;      // 128

    const int tid  = threadIdx.x;
    const int row0 = blockIdx.x * 64;
    const long long gnn0 = (long long)(LL - 1) * PP * HH;

    for (int i = tid; i < 2048; i += 256)
        ((float4*)s_w)[i] = ((const float4*)gl_w2)[i];
    for (int i = tid; i < 128; i += 256) {
        s_gb2[i] = gl_b2[i];
        s_ob1[i] = out_b1[i];
        s_ow2[i] = out_w2[i];
    }
    for (int i = tid; i < 64 * 64; i += 256) {
        int r = i >> 6, c = i & 63;
        s_g1[i] = lrelu(PO[row0 + r] * gl_w1[c] + gl_b1[c]);
    }
    for (int i = tid; i < 2048; i += 256) {
        int r = i >> 5, c4 = i & 31;
        float4 v = *((const float4*)(g_h + gnn0 + (long long)(row0 + r) * HH) + c4);
        *((float4*)(s_x + r * 256) + c4) = v;
    }
    __syncthreads();

    const int w = tid >> 5, l = tid & 31;
    const int r0 = w * 8, c0 = l * 4;

    {
        float acc[8][4];
#pragma unroll
        for (int r = 0; r < 8; r++) { acc[r][0] = acc[r][1] = acc[r][2] = acc[r][3] = 0.f; }
#pragma unroll 4
        for (int k = 0; k < 64; k += 2) {
            float4 w0  = *(const float4*)(s_w + k * 128 + c0);
            float4 w1v = *(const float4*)(s_w + (k + 1) * 128 + c0);
#pragma unroll
            for (int r = 0; r < 8; r++) {
                float2 a = *(const float2*)(s_g1 + (r0 + r) * 64 + k);
                acc[r][0] = fmaf(a.x, w0.x, acc[r][0]); acc[r][0] = fmaf(a.y, w1v.x, acc[r][0]);
                acc[r][1] = fmaf(a.x, w0.y, acc[r][1]); acc[r][1] = fmaf(a.y, w1v.y, acc[r][1]);
                acc[r][2] = fmaf(a.x, w0.z, acc[r][2]); acc[r][2] = fmaf(a.y, w1v.z, acc[r][2]);
                acc[r][3] = fmaf(a.x, w0.w, acc[r][3]); acc[r][3] = fmaf(a.y, w1v.w, acc[r][3]);
            }
        }
#pragma unroll
        for (int r = 0; r < 8; r++) {
            float4 o;
            o.x = acc[r][0] + s_gb2[c0 + 0];
            o.y = acc[r][1] + s_gb2[c0 + 1];
            o.z = acc[r][2] + s_gb2[c0 + 2];
            o.w = acc[r][3] + s_gb2[c0 + 3];
            *(float4*)(s_x + (r0 + r) * 256 + 128 + c0) = o;
        }
    }

    float acc[8][4];
#pragma unroll
    for (int r = 0; r < 8; r++) { acc[r][0] = acc[r][1] = acc[r][2] = acc[r][3] = 0.f; }
    for (int kt = 0; kt < 4; kt++) {
        __syncthreads();
        const float4* src = (const float4*)(out_w1 + kt * 64 * 128);
        for (int i = tid; i < 2048; i += 256) ((float4*)s_w)[i] = src[i];
        __syncthreads();
#pragma unroll 4
        for (int k = 0; k < 64; k += 2) {
            float4 w0  = *(const float4*)(s_w + k * 128 + c0);
            float4 w1v = *(const float4*)(s_w + (k + 1) * 128 + c0);
#pragma unroll
            for (int r = 0; r < 8; r++) {
                float2 a = *(const float2*)(s_x + (r0 + r) * 256 + kt * 64 + k);
                acc[r][0] = fmaf(a.x, w0.x, acc[r][0]); acc[r][0] = fmaf(a.y, w1v.x, acc[r][0]);
                acc[r][1] = fmaf(a.x, w0.y, acc[r][1]); acc[r][1] = fmaf(a.y, w1v.y, acc[r][1]);
                acc[r][2] = fmaf(a.x, w0.z, acc[r][2]); acc[r][2] = fmaf(a.y, w1v.z, acc[r][2]);
                acc[r][3] = fmaf(a.x, w0.w, acc[r][3]); acc[r][3] = fmaf(a.y, w1v.w, acc[r][3]);
            }
        }
    }
#pragma unroll
    for (int r = 0; r < 8; r++) {
        float* t = s_t + (r0 + r) * 132;
        t[c0 + 0] = lrelu(acc[r][0] + s_ob1[c0 + 0]);
        t[c0 + 1] = lrelu(acc[r][1] + s_ob1[c0 + 1]);
        t[c0 + 2] = lrelu(acc[r][2] + s_ob1[c0 + 2]);
        t[c0 + 3] = lrelu(acc[r][3] + s_ob1[c0 + 3]);
    }
    __syncthreads();

    if (tid < 64) {
        float s = out_b2[0];
        const float* t = s_t + tid * 132;
#pragma unroll 8
        for (int k = 0; k < 128; k++) s = fmaf(t[k], s_ow2[k], s);
        out[row0 + tid] = s;
    }
}

// ---------------------------------------------------------------------------
extern "C" void kernel_launch(void* const* d_in, const int* in_sizes, int n_in,
                              void* d_out, int out_size)
{
    // Disambiguate input ordering via in_sizes[3] (pred=3932160 vs pi_w1=64).
    int idx_pred, idx_ispo, wbase;
    if (in_sizes[3] == (LL - 1) * PP * KK) { idx_pred = 3; idx_ispo = 4; wbase = 5; }
    else                                   { idx_pred = 23; idx_ispo = 24; wbase = 3; }
    (void)idx_ispo;

    const float* delay  = (const float*)d_in[0];
    const float* feat   = (const float*)d_in[1];
    const float* PO     = (const float*)d_in[2];
    const int*   pred   = (const int*)d_in[idx_pred];
    const float* pi_w1  = (const float*)d_in[wbase + 0];
    const float* pi_b1  = (const float*)d_in[wbase + 1];
    const float* pi_w2  = (const float*)d_in[wbase + 2];
    const float* pi_b2  = (const float*)d_in[wbase + 3];
    const float* ne_w1  = (const float*)d_in[wbase + 4];
    const float* ne_b1  = (const float*)d_in[wbase + 5];
    const float* ne_w2  = (const float*)d_in[wbase + 6];
    const float* ne_b2  = (const float*)d_in[wbase + 7];
    const float* sf_w1  = (const float*)d_in[wbase + 8];
    const float* sf_b1  = (const float*)d_in[wbase + 9];
    const float* sf_w2  = (const float*)d_in[wbase + 10];
    const float* sf_b2  = (const float*)d_in[wbase + 11];
    const float* gl_w1  = (const float*)d_in[wbase + 12];
    const float* gl_b1  = (const float*)d_in[wbase + 13];
    const float* gl_w2  = (const float*)d_in[wbase + 14];
    const float* gl_b2  = (const float*)d_in[wbase + 15];
    const float* out_w1 = (const float*)d_in[wbase + 16];
    const float* out_b1 = (const float*)d_in[wbase + 17];
    const float* out_w2 = (const float*)d_in[wbase + 18];
    const float* out_b2 = (const float*)d_in[wbase + 19];
    float* out = (float*)d_out;

    const size_t sh_init  = (size_t)(4096 + 8192 + 128 + 8192) * 4;
    const size_t sh_layer = (size_t)5632 * 4;   // 22,528 B
    const size_t sh_final = (size_t)(16384 + 8192 + 8448 + 4096 + 128 + 128 + 128) * 4;

    cudaFuncSetAttribute(k_init,  cudaFuncAttributeMaxDynamicSharedMemorySize, (int)sh_init);
    cudaFuncSetAttribute(k_layer<false>, cudaFuncAttributeMaxDynamicSharedMemorySize, (int)sh_layer);
    cudaFuncSetAttribute(k_layer<true>,  cudaFuncAttributeMaxDynamicSharedMemorySize, (int)sh_layer);
    cudaFuncSetAttribute(k_all,   cudaFuncAttributeMaxDynamicSharedMemorySize, (int)sh_layer);
    cudaFuncSetAttribute(k_final, cudaFuncAttributeMaxDynamicSharedMemorySize, (int)sh_final);

    // Persistent path requires all NB blocks co-resident: verify via occupancy.
    int dev = 0, sms = 0, maxB = 0;
    cudaGetDevice(&dev);
    cudaDeviceGetAttribute(&sms, cudaDevAttrMultiProcessorCount, dev);
    cudaOccupancyMaxActiveBlocksPerMultiprocessor(&maxB, k_all, 128, sh_layer);
    const bool persistent = ((long long)maxB * sms >= NB);

    k_init<<<PP / 64, 256, sh_init>>>(delay, pi_w1, pi_b1, pi_w2, pi_b2, ne_w1);
    if (persistent) {
        k_reset<<<1, 1>>>();
        k_all<<<NB, 128, sh_layer>>>(pred, feat,
            ne_w1, ne_b1, ne_w2, ne_b2, sf_w1, sf_b1, sf_w2, sf_b2);
    } else {
        for (int i = 1; i < LL; i++) {
            const int* pl = pred + (long long)(i - 1) * PP * KK;
            if (i < LL - 1)
                k_layer<false><<<NB, 128, sh_layer>>>(i * PP, pl, feat,
                    ne_w1, ne_b1, ne_w2, ne_b2, sf_w1, sf_b1, sf_w2, sf_b2);
            else
                k_layer<true><<<NB, 128, sh_layer>>>(i * PP, pl, feat,
                    ne_w1, ne_b1, ne_w2, ne_b2, sf_w1, sf_b1, sf_w2, sf_b2);
        }
    }
    k_final<<<PP / 64, 256, sh_final>>>(PO, gl_w1, gl_b1, gl_w2, gl_b2,
                                        out_w1, out_b1, out_w2, out_b2, out);
}

// round 16
// speedup vs baseline: 1.0282x; 1.0282x over previous
#include <cuda_runtime.h>

#define PP 32768
#define LL 16
#define KK 8
#define HH 128
#define YW 64
#define NB (PP / 32)

// h only needed for layer 15 (final head); y carries layers 0..14.
__device__ float g_h[(long long)LL * PP * HH];   // 256 MiB
__device__ float g_y[(long long)LL * PP * YW];   // 128 MiB
// Folded constant weights (computed once per launch by k_pre)
__device__ float g_W0[64 * 64];    // pi_w2 @ ne_w1
__device__ float g_bY[64];         // pi_b2 @ ne_w1
__device__ float g_G[64 * 128];    // gl_w2 @ out_w1[128:256]
__device__ float g_bG[128];        // gl_b2 @ out_w1[128:256]

__device__ __forceinline__ float lrelu(float x) { return x > 0.0f ? x : 0.1f * x; }
__device__ __forceinline__ float relu_(float x) { return x > 0.0f ? x : 0.0f; }

// ---------------------------------------------------------------------------
// k_pre: fold constant weight products. One block, 256 threads.
// ---------------------------------------------------------------------------
__global__ void k_pre(const float* __restrict__ pi_w2, const float* __restrict__ pi_b2,
                      const float* __restrict__ ne_w1,
                      const float* __restrict__ gl_w2, const float* __restrict__ gl_b2,
                      const float* __restrict__ out_w1)
{
    const int tid = threadIdx.x;
    for (int o = tid; o < 64 * 64; o += 256) {
        int i = o >> 6, j = o & 63;
        float s0 = 0.f, s1 = 0.f, s2 = 0.f, s3 = 0.f;
        for (int k = 0; k < 128; k += 4) {
            s0 = fmaf(pi_w2[i * 128 + k + 0], ne_w1[(k + 0) * 64 + j], s0);
            s1 = fmaf(pi_w2[i * 128 + k + 1], ne_w1[(k + 1) * 64 + j], s1);
            s2 = fmaf(pi_w2[i * 128 + k + 2], ne_w1[(k + 2) * 64 + j], s2);
            s3 = fmaf(pi_w2[i * 128 + k + 3], ne_w1[(k + 3) * 64 + j], s3);
        }
        g_W0[o] = (s0 + s1) + (s2 + s3);
    }
    for (int j = tid; j < 64; j += 256) {
        float s0 = 0.f, s1 = 0.f;
        for (int k = 0; k < 128; k += 2) {
            s0 = fmaf(pi_b2[k],     ne_w1[k * 64 + j],       s0);
            s1 = fmaf(pi_b2[k + 1], ne_w1[(k + 1) * 64 + j], s1);
        }
        g_bY[j] = s0 + s1;
    }
    for (int o = tid; o < 64 * 128; o += 256) {
        int i = o >> 7, j = o & 127;
        float s0 = 0.f, s1 = 0.f, s2 = 0.f, s3 = 0.f;
        for (int k = 0; k < 128; k += 4) {
            s0 = fmaf(gl_w2[i * 128 + k + 0], out_w1[(128 + k + 0) * 128 + j], s0);
            s1 = fmaf(gl_w2[i * 128 + k + 1], out_w1[(128 + k + 1) * 128 + j], s1);
            s2 = fmaf(gl_w2[i * 128 + k + 2], out_w1[(128 + k + 2) * 128 + j], s2);
            s3 = fmaf(gl_w2[i * 128 + k + 3], out_w1[(128 + k + 3) * 128 + j], s3);
        }
        g_G[o] = (s0 + s1) + (s2 + s3);
    }
    for (int j = tid; j < 128; j += 256) {
        float s0 = 0.f, s1 = 0.f;
        for (int k = 0; k < 128; k += 2) {
            s0 = fmaf(gl_b2[k],     out_w1[(128 + k) * 128 + j],     s0);
            s1 = fmaf(gl_b2[k + 1], out_w1[(128 + k + 1) * 128 + j], s1);
        }
        g_bG[j] = s0 + s1;
    }
}

// ---------------------------------------------------------------------------
// k_init: y0 = lrelu(delay*pi_w1+pi_b1) @ W0 + bY   (folded; 64-wide only)
// 128 thr / 32 rows / grid 1024 / 8KB smem.
// ---------------------------------------------------------------------------
__global__ void __launch_bounds__(128, 7)
k_init(const float* __restrict__ delay,
       const float* __restrict__ pi_w1, const float* __restrict__ pi_b1)
{
    extern __shared__ float smem[];   // s_t1: 32*64 = 2048 floats
    const int tid  = threadIdx.x;
    const int row0 = blockIdx.x * 32;

    for (int i = tid; i < 2048; i += 128) {
        int r = i >> 6, c = i & 63;
        smem[i] = lrelu(delay[row0 + r] * pi_w1[c] + pi_b1[c]);
    }
    __syncthreads();

    const int w = tid >> 5, l = tid & 31;
    const int r1 = w * 8 + (l >> 4) * 4;
    const int cg = (l & 15) * 4;

    float acc[4][4];
#pragma unroll
    for (int i = 0; i < 4; i++)
#pragma unroll
        for (int c = 0; c < 4; c++) acc[i][c] = 0.f;

#pragma unroll 4
    for (int k = 0; k < 64; k += 4) {
        float4 wv0 = *(const float4*)(g_W0 + (k + 0) * 64 + cg);
        float4 wv1 = *(const float4*)(g_W0 + (k + 1) * 64 + cg);
        float4 wv2 = *(const float4*)(g_W0 + (k + 2) * 64 + cg);
        float4 wv3 = *(const float4*)(g_W0 + (k + 3) * 64 + cg);
#pragma unroll
        for (int i = 0; i < 4; i++) {
            float4 a = *(const float4*)(smem + (r1 + i) * 64 + k);
            acc[i][0] = fmaf(a.x, wv0.x, acc[i][0]); acc[i][0] = fmaf(a.y, wv1.x, acc[i][0]);
            acc[i][0] = fmaf(a.z, wv2.x, acc[i][0]); acc[i][0] = fmaf(a.w, wv3.x, acc[i][0]);
            acc[i][1] = fmaf(a.x, wv0.y, acc[i][1]); acc[i][1] = fmaf(a.y, wv1.y, acc[i][1]);
            acc[i][1] = fmaf(a.z, wv2.y, acc[i][1]); acc[i][1] = fmaf(a.w, wv3.y, acc[i][1]);
            acc[i][2] = fmaf(a.x, wv0.z, acc[i][2]); acc[i][2] = fmaf(a.y, wv1.z, acc[i][2]);
            acc[i][2] = fmaf(a.z, wv2.z, acc[i][2]); acc[i][2] = fmaf(a.w, wv3.z, acc[i][2]);
            acc[i][3] = fmaf(a.x, wv0.w, acc[i][3]); acc[i][3] = fmaf(a.y, wv1.w, acc[i][3]);
            acc[i][3] = fmaf(a.z, wv2.w, acc[i][3]); acc[i][3] = fmaf(a.w, wv3.w, acc[i][3]);
        }
    }
    float4 b = *(const float4*)(g_bY + cg);
#pragma unroll
    for (int i = 0; i < 4; i++)
        *(float4*)(g_y + (long long)(row0 + r1 + i) * YW + cg) =
            make_float4(acc[i][0] + b.x, acc[i][1] + b.y, acc[i][2] + b.z, acc[i][3] + b.w);
}

// ---------------------------------------------------------------------------
// k_layer<LAST>: R14-proven (unchanged). 128 thr / 32 rows / 22.5KB / 7 blk/SM.
// ---------------------------------------------------------------------------
template <bool LAST>
__global__ void __launch_bounds__(128, 7)
k_layer(int lo,
        const int*   __restrict__ pred,
        const float* __restrict__ feat,
        const float* __restrict__ ne_w1, const float* __restrict__ ne_b1,
        const float* __restrict__ ne_w2, const float* __restrict__ ne_b2,
        const float* __restrict__ sf_w1, const float* __restrict__ sf_b1,
        const float* __restrict__ sf_w2, const float* __restrict__ sf_b2)
{
    extern __shared__ float smem[];
    float* s_t   = smem;            // 32*128 = 4096 (t, later hn)
    float* s_ft  = smem + 4096;     // 32*32 = 1024
    float* s_b1  = smem + 5120;     // 128
    float* s_b2  = smem + 5248;     // 128
    int*   s_pred = (int*)(smem + 5376);  // 256

    const int tid  = threadIdx.x;
    const int row0 = blockIdx.x * 32;

    for (int i = tid; i < 256; i += 128) {
        int r = i >> 3, c4 = i & 7;
        ((float4*)(s_ft + r * 32))[c4] =
            *((const float4*)(feat + (long long)(lo + row0 + r) * 32) + c4);
    }
    for (int i = tid; i < 256; i += 128)
        s_pred[i] = pred[(long long)row0 * KK + i];
    if (tid < 128) {
        s_b1[tid] = (tid < 64) ? ne_b1[tid] : sf_b1[tid - 64];
        s_b2[tid] = ne_b2[tid] + sf_b2[tid];
    }
    __syncthreads();

    float4* t4 = (float4*)s_t;
#pragma unroll
    for (int j = 0; j < 4; j++) {
        int task = tid + j * 128;
        int r = task >> 4, c4 = task & 15;
        const int* pr = s_pred + r * 8;
        float x = 0.f, y = 0.f, z = 0.f, s = 0.f;
#pragma unroll
        for (int k = 0; k < 8; k++) {
            const float4 v = *((const float4*)(g_y + (long long)pr[k] * YW) + c4);
            x += v.x; y += v.y; z += v.z; s += v.w;
        }
        const int c = c4 * 4;
        float4 o;
        o.x = lrelu(x * 0.125f + s_b1[c + 0]);
        o.y = lrelu(y * 0.125f + s_b1[c + 1]);
        o.z = lrelu(z * 0.125f + s_b1[c + 2]);
        o.w = lrelu(s * 0.125f + s_b1[c + 3]);
        t4[r * 32 + c4] = o;
    }

    const int w = tid >> 5, l = tid & 31;
    const int r0 = w * 8;
    const int r1 = r0 + (l >> 4) * 4;
    const int cg = (l & 15) * 4;

    {
        float accB[4][4];
#pragma unroll
        for (int i = 0; i < 4; i++)
#pragma unroll
            for (int c = 0; c < 4; c++) accB[i][c] = 0.f;
#pragma unroll 2
        for (int k = 0; k < 32; k += 4) {
            float4 wv0 = *(const float4*)(sf_w1 + (k + 0) * 64 + cg);
            float4 wv1 = *(const float4*)(sf_w1 + (k + 1) * 64 + cg);
            float4 wv2 = *(const float4*)(sf_w1 + (k + 2) * 64 + cg);
            float4 wv3 = *(const float4*)(sf_w1 + (k + 3) * 64 + cg);
#pragma unroll
            for (int i = 0; i < 4; i++) {
                float4 a = *(const float4*)(s_ft + (r1 + i) * 32 + k);
                accB[i][0] = fmaf(a.x, wv0.x, accB[i][0]); accB[i][0] = fmaf(a.y, wv1.x, accB[i][0]);
                accB[i][0] = fmaf(a.z, wv2.x, accB[i][0]); accB[i][0] = fmaf(a.w, wv3.x, accB[i][0]);
                accB[i][1] = fmaf(a.x, wv0.y, accB[i][1]); accB[i][1] = fmaf(a.y, wv1.y, accB[i][1]);
                accB[i][1] = fmaf(a.z, wv2.y, accB[i][1]); accB[i][1] = fmaf(a.w, wv3.y, accB[i][1]);
                accB[i][2] = fmaf(a.x, wv0.z, accB[i][2]); accB[i][2] = fmaf(a.y, wv1.z, accB[i][2]);
                accB[i][2] = fmaf(a.z, wv2.z, accB[i][2]); accB[i][2] = fmaf(a.w, wv3.z, accB[i][2]);
                accB[i][3] = fmaf(a.x, wv0.w, accB[i][3]); accB[i][3] = fmaf(a.y, wv1.w, accB[i][3]);
                accB[i][3] = fmaf(a.z, wv2.w, accB[i][3]); accB[i][3] = fmaf(a.w, wv3.w, accB[i][3]);
            }
        }
#pragma unroll
        for (int i = 0; i < 4; i++) {
            float4 o;
            o.x = lrelu(accB[i][0] + s_b1[64 + cg + 0]);
            o.y = lrelu(accB[i][1] + s_b1[64 + cg + 1]);
            o.z = lrelu(accB[i][2] + s_b1[64 + cg + 2]);
            o.w = lrelu(accB[i][3] + s_b1[64 + cg + 3]);
            *(float4*)(s_t + (r1 + i) * 128 + 64 + cg) = o;
        }
    }
    __syncthreads();

    const int c0 = l * 4;
    float acc[8][4];
#pragma unroll
    for (int r = 0; r < 8; r++) { acc[r][0] = acc[r][1] = acc[r][2] = acc[r][3] = 0.f; }

#pragma unroll 2
    for (int k = 0; k < 64; k += 4) {
        float4 wv0 = *(const float4*)(ne_w2 + (k + 0) * 128 + c0);
        float4 wv1 = *(const float4*)(ne_w2 + (k + 1) * 128 + c0);
        float4 wv2 = *(const float4*)(ne_w2 + (k + 2) * 128 + c0);
        float4 wv3 = *(const float4*)(ne_w2 + (k + 3) * 128 + c0);
#pragma unroll
        for (int r = 0; r < 8; r++) {
            float4 a = *(const float4*)(s_t + (r0 + r) * 128 + k);
            acc[r][0] = fmaf(a.x, wv0.x, acc[r][0]); acc[r][0] = fmaf(a.y, wv1.x, acc[r][0]);
            acc[r][0] = fmaf(a.z, wv2.x, acc[r][0]); acc[r][0] = fmaf(a.w, wv3.x, acc[r][0]);
            acc[r][1] = fmaf(a.x, wv0.y, acc[r][1]); acc[r][1] = fmaf(a.y, wv1.y, acc[r][1]);
            acc[r][1] = fmaf(a.z, wv2.y, acc[r][1]); acc[r][1] = fmaf(a.w, wv3.y, acc[r][1]);
            acc[r][2] = fmaf(a.x, wv0.z, acc[r][2]); acc[r][2] = fmaf(a.y, wv1.z, acc[r][2]);
            acc[r][2] = fmaf(a.z, wv2.z, acc[r][2]); acc[r][2] = fmaf(a.w, wv3.z, acc[r][2]);
            acc[r][3] = fmaf(a.x, wv0.w, acc[r][3]); acc[r][3] = fmaf(a.y, wv1.w, acc[r][3]);
            acc[r][3] = fmaf(a.z, wv2.w, acc[r][3]); acc[r][3] = fmaf(a.w, wv3.w, acc[r][3]);
        }
    }
#pragma unroll 2
    for (int k = 0; k < 64; k += 4) {
        float4 wv0 = *(const float4*)(sf_w2 + (k + 0) * 128 + c0);
        float4 wv1 = *(const float4*)(sf_w2 + (k + 1) * 128 + c0);
        float4 wv2 = *(const float4*)(sf_w2 + (k + 2) * 128 + c0);
        float4 wv3 = *(const float4*)(sf_w2 + (k + 3) * 128 + c0);
#pragma unroll
        for (int r = 0; r < 8; r++) {
            float4 a = *(const float4*)(s_t + (r0 + r) * 128 + 64 + k);
            acc[r][0] = fmaf(a.x, wv0.x, acc[r][0]); acc[r][0] = fmaf(a.y, wv1.x, acc[r][0]);
            acc[r][0] = fmaf(a.z, wv2.x, acc[r][0]); acc[r][0] = fmaf(a.w, wv3.x, acc[r][0]);
            acc[r][1] = fmaf(a.x, wv0.y, acc[r][1]); acc[r][1] = fmaf(a.y, wv1.y, acc[r][1]);
            acc[r][1] = fmaf(a.z, wv2.y, acc[r][1]); acc[r][1] = fmaf(a.w, wv3.y, acc[r][1]);
            acc[r][2] = fmaf(a.x, wv0.z, acc[r][2]); acc[r][2] = fmaf(a.y, wv1.z, acc[r][2]);
            acc[r][2] = fmaf(a.z, wv2.z, acc[r][2]); acc[r][2] = fmaf(a.w, wv3.z, acc[r][2]);
            acc[r][3] = fmaf(a.x, wv0.w, acc[r][3]); acc[r][3] = fmaf(a.y, wv1.w, acc[r][3]);
            acc[r][3] = fmaf(a.z, wv2.w, acc[r][3]); acc[r][3] = fmaf(a.w, wv3.w, acc[r][3]);
        }
    }

    if (LAST) {
#pragma unroll
        for (int r = 0; r < 8; r++) {
            float4 o;
            o.x = acc[r][0] + s_b2[c0 + 0];
            o.y = acc[r][1] + s_b2[c0 + 1];
            o.z = acc[r][2] + s_b2[c0 + 2];
            o.w = acc[r][3] + s_b2[c0 + 3];
            *(float4*)(g_h + (long long)(lo + row0 + r0 + r) * HH + c0) = o;
        }
    } else {
#pragma unroll
        for (int r = 0; r < 8; r++) {
            float4 o;
            o.x = relu_(acc[r][0] + s_b2[c0 + 0]);
            o.y = relu_(acc[r][1] + s_b2[c0 + 1]);
            o.z = relu_(acc[r][2] + s_b2[c0 + 2]);
            o.w = relu_(acc[r][3] + s_b2[c0 + 3]);
            *(float4*)(s_t + (r0 + r) * 128 + c0) = o;
        }
        __syncwarp();

        float accY[4][4];
#pragma unroll
        for (int i = 0; i < 4; i++)
#pragma unroll
            for (int c = 0; c < 4; c++) accY[i][c] = 0.f;
#pragma unroll 2
        for (int k = 0; k < 128; k += 4) {
            float4 wv0 = *(const float4*)(ne_w1 + (k + 0) * 64 + cg);
            float4 wv1 = *(const float4*)(ne_w1 + (k + 1) * 64 + cg);
            float4 wv2 = *(const float4*)(ne_w1 + (k + 2) * 64 + cg);
            float4 wv3 = *(const float4*)(ne_w1 + (k + 3) * 64 + cg);
#pragma unroll
            for (int i = 0; i < 4; i++) {
                float4 a = *(const float4*)(s_t + (r1 + i) * 128 + k);
                accY[i][0] = fmaf(a.x, wv0.x, accY[i][0]); accY[i][0] = fmaf(a.y, wv1.x, accY[i][0]);
                accY[i][0] = fmaf(a.z, wv2.x, accY[i][0]); accY[i][0] = fmaf(a.w, wv3.x, accY[i][0]);
                accY[i][1] = fmaf(a.x, wv0.y, accY[i][1]); accY[i][1] = fmaf(a.y, wv1.y, accY[i][1]);
                accY[i][1] = fmaf(a.z, wv2.y, accY[i][1]); accY[i][1] = fmaf(a.w, wv3.y, accY[i][1]);
                accY[i][2] = fmaf(a.x, wv0.z, accY[i][2]); accY[i][2] = fmaf(a.y, wv1.z, accY[i][2]);
                accY[i][2] = fmaf(a.z, wv2.z, accY[i][2]); accY[i][2] = fmaf(a.w, wv3.z, accY[i][2]);
                accY[i][3] = fmaf(a.x, wv0.w, accY[i][3]); accY[i][3] = fmaf(a.y, wv1.w, accY[i][3]);
                accY[i][3] = fmaf(a.z, wv2.w, accY[i][3]); accY[i][3] = fmaf(a.w, wv3.w, accY[i][3]);
            }
        }
#pragma unroll
        for (int i = 0; i < 4; i++)
            *(float4*)(g_y + (long long)(lo + row0 + r1 + i) * YW + cg) =
                make_float4(accY[i][0], accY[i][1], accY[i][2], accY[i][3]);
    }
}

// ---------------------------------------------------------------------------
// k_final: folded head. 128 thr / 32 rows / grid 1024 / 25.6KB -> 7 blk/SM.
//   g1 = lrelu(PO*gl_w1+gl_b1)                      (64)
//   t  = lrelu(h_gnn@out_w1[0:128] + g1@G + (out_b1+bG))   (128)
//   out = t . out_w2 + out_b2
// ---------------------------------------------------------------------------
__global__ void __launch_bounds__(128, 7)
k_final(const float* __restrict__ PO,
        const float* __restrict__ gl_w1, const float* __restrict__ gl_b1,
        const float* __restrict__ out_w1, const float* __restrict__ out_b1,
        const float* __restrict__ out_w2, const float* __restrict__ out_b2,
        float* __restrict__ out)
{
    extern __shared__ float smem[];
    float* s_x  = smem;             // 32*128 = 4096 (h_gnn, later t)
    float* s_g1 = smem + 4096;      // 32*64  = 2048
    float* s_b  = smem + 6144;      // 128 (out_b1 + bG)
    float* s_w2 = smem + 6272;      // 128
    // total 6400 floats = 25600 B

    const int tid  = threadIdx.x;
    const int row0 = blockIdx.x * 32;
    const long long gnn0 = (long long)(LL - 1) * PP * HH;

    for (int i = tid; i < 1024; i += 128) {
        int r = i >> 5, c4 = i & 31;
        ((float4*)(s_x + r * 128))[c4] =
            *((const float4*)(g_h + gnn0 + (long long)(row0 + r) * HH) + c4);
    }
    for (int i = tid; i < 2048; i += 128) {
        int r = i >> 6, c = i & 63;
        s_g1[i] = lrelu(PO[row0 + r] * gl_w1[c] + gl_b1[c]);
    }
    if (tid < 128) {
        s_b[tid]  = out_b1[tid] + g_bG[tid];
        s_w2[tid] = out_w2[tid];
    }
    __syncthreads();

    const int w = tid >> 5, l = tid & 31;
    const int r0 = w * 8, c0 = l * 4;

    float acc[8][4];
#pragma unroll
    for (int r = 0; r < 8; r++) { acc[r][0] = acc[r][1] = acc[r][2] = acc[r][3] = 0.f; }

    // h_gnn @ out_w1[0:128]  (k=128, weights direct from global)
#pragma unroll 2
    for (int k = 0; k < 128; k += 4) {
        float4 wv0 = *(const float4*)(out_w1 + (k + 0) * 128 + c0);
        float4 wv1 = *(const float4*)(out_w1 + (k + 1) * 128 + c0);
        float4 wv2 = *(const float4*)(out_w1 + (k + 2) * 128 + c0);
        float4 wv3 = *(const float4*)(out_w1 + (k + 3) * 128 + c0);
#pragma unroll
        for (int r = 0; r < 8; r++) {
            float4 a = *(const float4*)(s_x + (r0 + r) * 128 + k);
            acc[r][0] = fmaf(a.x, wv0.x, acc[r][0]); acc[r][0] = fmaf(a.y, wv1.x, acc[r][0]);
            acc[r][0] = fmaf(a.z, wv2.x, acc[r][0]); acc[r][0] = fmaf(a.w, wv3.x, acc[r][0]);
            acc[r][1] = fmaf(a.x, wv0.y, acc[r][1]); acc[r][1] = fmaf(a.y, wv1.y, acc[r][1]);
            acc[r][1] = fmaf(a.z, wv2.y, acc[r][1]); acc[r][1] = fmaf(a.w, wv3.y, acc[r][1]);
            acc[r][2] = fmaf(a.x, wv0.z, acc[r][2]); acc[r][2] = fmaf(a.y, wv1.z, acc[r][2]);
            acc[r][2] = fmaf(a.z, wv2.z, acc[r][2]); acc[r][2] = fmaf(a.w, wv3.z, acc[r][2]);
            acc[r][3] = fmaf(a.x, wv0.w, acc[r][3]); acc[r][3] = fmaf(a.y, wv1.w, acc[r][3]);
            acc[r][3] = fmaf(a.z, wv2.w, acc[r][3]); acc[r][3] = fmaf(a.w, wv3.w, acc[r][3]);
        }
    }
    // + g1 @ G  (k=64)
#pragma unroll 2
    for (int k = 0; k < 64; k += 4) {
        float4 wv0 = *(const float4*)(g_G + (k + 0) * 128 + c0);
        float4 wv1 = *(const float4*)(g_G + (k + 1) * 128 + c0);
        float4 wv2 = *(const float4*)(g_G + (k + 2) * 128 + c0);
        float4 wv3 = *(const float4*)(g_G + (k + 3) * 128 + c0);
#pragma unroll
        for (int r = 0; r < 8; r++) {
            float4 a = *(const float4*)(s_g1 + (r0 + r) * 64 + k);
            acc[r][0] = fmaf(a.x, wv0.x, acc[r][0]); acc[r][0] = fmaf(a.y, wv1.x, acc[r][0]);
            acc[r][0] = fmaf(a.z, wv2.x, acc[r][0]); acc[r][0] = fmaf(a.w, wv3.x, acc[r][0]);
            acc[r][1] = fmaf(a.x, wv0.y, acc[r][1]); acc[r][1] = fmaf(a.y, wv1.y, acc[r][1]);
            acc[r][1] = fmaf(a.z, wv2.y, acc[r][1]); acc[r][1] = fmaf(a.w, wv3.y, acc[r][1]);
            acc[r][2] = fmaf(a.x, wv0.z, acc[r][2]); acc[r][2] = fmaf(a.y, wv1.z, acc[r][2]);
            acc[r][2] = fmaf(a.z, wv2.z, acc[r][2]); acc[r][2] = fmaf(a.w, wv3.z, acc[r][2]);
            acc[r][3] = fmaf(a.x, wv0.w, acc[r][3]); acc[r][3] = fmaf(a.y, wv1.w, acc[r][3]);
            acc[r][3] = fmaf(a.z, wv2.w, acc[r][3]); acc[r][3] = fmaf(a.w, wv3.w, acc[r][3]);
        }
    }

    __syncwarp();   // all lanes of this warp done reading own s_x rows
#pragma unroll
    for (int r = 0; r < 8; r++) {
        float4 o;
        o.x = lrelu(acc[r][0] + s_b[c0 + 0]);
        o.y = lrelu(acc[r][1] + s_b[c0 + 1]);
        o.z = lrelu(acc[r][2] + s_b[c0 + 2]);
        o.w = lrelu(acc[r][3] + s_b[c0 + 3]);
        *(float4*)(s_x + (r0 + r) * 128 + c0) = o;   // t overwrites own rows
    }
    __syncwarp();

    const float b2v = out_b2[0];
#pragma unroll
    for (int r = 0; r < 8; r++) {
        const float* t = s_x + (r0 + r) * 128;
        float v = t[l] * s_w2[l] + t[l + 32] * s_w2[l + 32]
                + t[l + 64] * s_w2[l + 64] + t[l + 96] * s_w2[l + 96];
#pragma unroll
        for (int off = 16; off > 0; off >>= 1)
            v += __shfl_down_sync(0xffffffffu, v, off);
        if (l == 0) out[row0 + r0 + r] = v + b2v;
    }
}

// ---------------------------------------------------------------------------
extern "C" void kernel_launch(void* const* d_in, const int* in_sizes, int n_in,
                              void* d_out, int out_size)
{
    // Disambiguate input ordering via in_sizes[3] (pred=3932160 vs pi_w1=64).
    int idx_pred, idx_ispo, wbase;
    if (in_sizes[3] == (LL - 1) * PP * KK) { idx_pred = 3; idx_ispo = 4; wbase = 5; }
    else                                   { idx_pred = 23; idx_ispo = 24; wbase = 3; }
    (void)idx_ispo;

    const float* delay  = (const float*)d_in[0];
    const float* feat   = (const float*)d_in[1];
    const float* PO     = (const float*)d_in[2];
    const int*   pred   = (const int*)d_in[idx_pred];
    const float* pi_w1  = (const float*)d_in[wbase + 0];
    const float* pi_b1  = (const float*)d_in[wbase + 1];
    const float* pi_w2  = (const float*)d_in[wbase + 2];
    const float* pi_b2  = (const float*)d_in[wbase + 3];
    const float* ne_w1  = (const float*)d_in[wbase + 4];
    const float* ne_b1  = (const float*)d_in[wbase + 5];
    const float* ne_w2  = (const float*)d_in[wbase + 6];
    const float* ne_b2  = (const float*)d_in[wbase + 7];
    const float* sf_w1  = (const float*)d_in[wbase + 8];
    const float* sf_b1  = (const float*)d_in[wbase + 9];
    const float* sf_w2  = (const float*)d_in[wbase + 10];
    const float* sf_b2  = (const float*)d_in[wbase + 11];
    const float* gl_w1  = (const float*)d_in[wbase + 12];
    const float* gl_b1  = (const float*)d_in[wbase + 13];
    const float* gl_w2  = (const float*)d_in[wbase + 14];
    const float* gl_b2  = (const float*)d_in[wbase + 15];
    const float* out_w1 = (const float*)d_in[wbase + 16];
    const float* out_b1 = (const float*)d_in[wbase + 17];
    const float* out_w2 = (const float*)d_in[wbase + 18];
    const float* out_b2 = (const float*)d_in[wbase + 19];
    float* out = (float*)d_out;

    const size_t sh_init  = (size_t)2048 * 4;    //  8,192 B
    const size_t sh_layer = (size_t)5632 * 4;    // 22,528 B
    const size_t sh_final = (size_t)6400 * 4;    // 25,600 B

    cudaFuncSetAttribute(k_init,  cudaFuncAttributeMaxDynamicSharedMemorySize, (int)sh_init);
    cudaFuncSetAttribute(k_layer<false>, cudaFuncAttributeMaxDynamicSharedMemorySize, (int)sh_layer);
    cudaFuncSetAttribute(k_layer<true>,  cudaFuncAttributeMaxDynamicSharedMemorySize, (int)sh_layer);
    cudaFuncSetAttribute(k_final, cudaFuncAttributeMaxDynamicSharedMemorySize, (int)sh_final);

    k_pre<<<1, 256>>>(pi_w2, pi_b2, ne_w1, gl_w2, gl_b2, out_w1);
    k_init<<<NB, 128, sh_init>>>(delay, pi_w1, pi_b1);
    for (int i = 1; i < LL; i++) {
        const int* pl = pred + (long long)(i - 1) * PP * KK;
        if (i < LL - 1)
            k_layer<false><<<NB, 128, sh_layer>>>(i * PP, pl, feat,
                ne_w1, ne_b1, ne_w2, ne_b2, sf_w1, sf_b1, sf_w2, sf_b2);
        else
            k_layer<true><<<NB, 128, sh_layer>>>(i * PP, pl, feat,
                ne_w1, ne_b1, ne_w2, ne_b2, sf_w1, sf_b1, sf_w2, sf_b2);
    }
    k_final<<<NB, 128, sh_final>>>(PO, gl_w1, gl_b1, out_w1, out_b1, out_w2, out_b2, out);
}